// round 2
// baseline (speedup 1.0000x reference)
#include <cuda_runtime.h>
#include <math.h>

constexpr int NN = 1024, DD = 256, HH = 64, CC = 20, LL = 3;

constexpr long OUT_STACKED = 0;
constexpr long OUT_FINAL   = (long)NN * CC * HH;
constexpr long OUT_ATTN    = OUT_FINAL + (long)NN * HH;
constexpr long OUT_PRED    = OUT_ATTN + (long)NN * CC;

// scratch offsets (floats)
constexpr long O_T1    = 0;
constexpr long O_NE    = O_T1 + (long)NN * HH;
constexpr long O_NP    = O_NE + (long)NN * HH;
constexpr long O_S     = O_NP + (long)CC * NN * HH;
constexpr long O_PREGH = O_S + 2L * CC * NN * HH;
constexpr long O_CTX   = O_PREGH + (long)CC * NN * 256;
constexpr long O_GI    = O_CTX + (long)CC * NN * HH;
constexpr long O_WP1   = O_GI + (long)CC * NN * 192;
constexpr long O_BP1   = O_WP1 + (long)CC * 64 * 256;
constexpr long O_WIHT  = O_BP1 + (long)CC * 256;
constexpr long O_MASK  = O_WIHT + (long)CC * 64 * 192;
constexpr long SCRATCH = O_MASK + NN;

__device__ float g_scratch[SCRATCH];

__global__ void zero_kernel(float* __restrict__ p, int n) {
    for (int i = blockIdx.x * blockDim.x + threadIdx.x; i < n; i += gridDim.x * blockDim.x)
        p[i] = 0.f;
}

__global__ void scatter_mask_kernel(const int* __restrict__ edges, int E, float* __restrict__ mask) {
    int i = blockIdx.x * blockDim.x + threadIdx.x;
    if (i < E) mask[edges[2 * i + 1]] = 1.0f;
}

// Wpack1[c][k][j]: j<64 -> Wa1[c][k][j]; j>=64 -> Whh[c][j-64][k]. WihT[c][k][j] = Wih[c][j][k].
__global__ void pack_kernel(const float* __restrict__ Wa1, const float* __restrict__ Whh,
                            const float* __restrict__ ba1, const float* __restrict__ bhh,
                            const float* __restrict__ Wih,
                            float* __restrict__ Wp1, float* __restrict__ bp1,
                            float* __restrict__ WihT) {
    int stride = gridDim.x * blockDim.x;
    int idx = blockIdx.x * blockDim.x + threadIdx.x;
    for (int t = idx; t < CC * 64 * 256; t += stride) {
        int c = t / (64 * 256), r = t % (64 * 256), k = r / 256, j = r % 256;
        Wp1[t] = (j < 64) ? Wa1[((long)c * 128 + k) * 64 + j]
                          : Whh[((long)c * 192 + (j - 64)) * 64 + k];
    }
    for (int t = idx; t < CC * 64 * 192; t += stride) {
        int c = t / (64 * 192), r = t % (64 * 192), k = r / 192, j = r % 192;
        WihT[t] = Wih[((long)c * 192 + j) * 64 + k];
    }
    for (int t = idx; t < CC * 256; t += stride) {
        int c = t / 256, j = t % 256;
        bp1[t] = (j < 64) ? ba1[c * 64 + j] : bhh[c * 192 + (j - 64)];
    }
}

// Out[c] = act(A[c] (64-row tiles, lda) @ W[c] (ldw) + bias). 64x64 block tile, 4x4/thread, BK=16.
template<int ACT>
__global__ void __launch_bounds__(256) gemm_tiled(
    const float* __restrict__ A, long aCS, int lda,
    const float* __restrict__ W, long wCS, int ldw,
    const float* __restrict__ Bv, long bCS,
    float* __restrict__ Out, long oCS, int ldo, int K) {
    __shared__ float As[16 * 68];
    __shared__ float Bs[16 * 64];
    const int c = blockIdx.z;
    A += (long)c * aCS; W += (long)c * wCS; Out += (long)c * oCS;
    if (Bv) Bv += (long)c * bCS;
    const int row0 = blockIdx.y * 64, col0 = blockIdx.x * 64;
    const int tid = threadIdx.x, tb = tid >> 4, tn = tid & 15;
    float acc[4][4] = {};
    for (int k0 = 0; k0 < K; k0 += 16) {
        int n = tid >> 2, kg = tid & 3;
        float4 av = *(const float4*)(A + (long)(row0 + n) * lda + k0 + 4 * kg);
        As[(4 * kg + 0) * 68 + n] = av.x;
        As[(4 * kg + 1) * 68 + n] = av.y;
        As[(4 * kg + 2) * 68 + n] = av.z;
        As[(4 * kg + 3) * 68 + n] = av.w;
        *(float4*)(Bs + tb * 64 + 4 * tn) = *(const float4*)(W + (long)(k0 + tb) * ldw + col0 + 4 * tn);
        __syncthreads();
#pragma unroll
        for (int k = 0; k < 16; k++) {
            float4 a = *(const float4*)(As + k * 68 + 4 * tb);
            float4 b = *(const float4*)(Bs + k * 64 + 4 * tn);
            float aa[4] = {a.x, a.y, a.z, a.w}, bb[4] = {b.x, b.y, b.z, b.w};
#pragma unroll
            for (int i = 0; i < 4; i++)
#pragma unroll
                for (int j = 0; j < 4; j++)
                    acc[i][j] = fmaf(aa[i], bb[j], acc[i][j]);
        }
        __syncthreads();
    }
    float bb[4] = {0.f, 0.f, 0.f, 0.f};
    if (Bv) {
        bb[0] = Bv[col0 + 4 * tn]; bb[1] = Bv[col0 + 4 * tn + 1];
        bb[2] = Bv[col0 + 4 * tn + 2]; bb[3] = Bv[col0 + 4 * tn + 3];
    }
#pragma unroll
    for (int i = 0; i < 4; i++) {
        float t0 = acc[i][0] + bb[0], t1 = acc[i][1] + bb[1];
        float t2 = acc[i][2] + bb[2], t3 = acc[i][3] + bb[3];
        if (ACT == 1) { t0 = fmaxf(t0, 0.f); t1 = fmaxf(t1, 0.f); t2 = fmaxf(t2, 0.f); t3 = fmaxf(t3, 0.f); }
        float4 v = make_float4(t0, t1, t2, t3);
        *(float4*)(Out + (long)(row0 + 4 * tb + i) * ldo + col0 + 4 * tn) = v;
    }
}

constexpr int SMEM_ATTN = (64 * 68 + 64 * 68 + 64 * 64 + 64 + 64) * 4;

// Fused attention step: score[b,n]=(sum_h relu(pre+np)*wa2 + ba2)*mask[n]; ctx=softmax@ne.
__global__ void __launch_bounds__(256) attn_step_kernel(
    const float* __restrict__ pregh, const float* __restrict__ np_,
    const float* __restrict__ ne, const float* __restrict__ Wa2,
    const float* __restrict__ ba2, const float* __restrict__ mask,
    float* __restrict__ ctx) {
    extern __shared__ float sm[];
    float* Pt  = sm;               // [64h][68] pre transposed
    float* Qt  = Pt + 64 * 68;     // [64h][68] np transposed; reused as PB[b][68]
    float* NE  = Qt + 64 * 68;     // [64n][64h]
    float* ws  = NE + 64 * 64;
    float* msk = ws + 64;

    const int c = blockIdx.y, b0 = blockIdx.x * 64;
    const int tid = threadIdx.x, tb = tid >> 4, tn = tid & 15;

    if (tid < 64) ws[tid] = Wa2[c * 64 + tid];
    const float bias2 = ba2[c];

    const float* preB = pregh + ((long)c * 1024 + b0) * 256;
#pragma unroll
    for (int r = 0; r < 4; r++) {
        int idx = tid + r * 256, h = idx & 63, b4 = idx >> 6;
        float4 v;
        v.x = preB[(long)(4 * b4 + 0) * 256 + h];
        v.y = preB[(long)(4 * b4 + 1) * 256 + h];
        v.z = preB[(long)(4 * b4 + 2) * 256 + h];
        v.w = preB[(long)(4 * b4 + 3) * 256 + h];
        *(float4*)(Pt + h * 68 + 4 * b4) = v;
    }

    float m_run[4], l_run[4], ctxa[4][4];
#pragma unroll
    for (int i = 0; i < 4; i++) {
        m_run[i] = -1e30f; l_run[i] = 0.f;
#pragma unroll
        for (int j = 0; j < 4; j++) ctxa[i][j] = 0.f;
    }

    const float* npc = np_ + (long)c * 1024 * 64;

    for (int nt = 0; nt < 1024; nt += 64) {
        __syncthreads();
#pragma unroll
        for (int r = 0; r < 4; r++) {
            int idx = tid + r * 256, h = idx & 63, n4 = idx >> 6;
            float4 v;
            v.x = npc[(long)(nt + 4 * n4 + 0) * 64 + h];
            v.y = npc[(long)(nt + 4 * n4 + 1) * 64 + h];
            v.z = npc[(long)(nt + 4 * n4 + 2) * 64 + h];
            v.w = npc[(long)(nt + 4 * n4 + 3) * 64 + h];
            *(float4*)(Qt + h * 68 + 4 * n4) = v;
            int n = idx >> 4, h4 = idx & 15;
            *(float4*)(NE + n * 64 + 4 * h4) = *(const float4*)(ne + (long)(nt + n) * 64 + 4 * h4);
        }
        if (tid < 64) msk[tid] = mask[nt + tid];
        __syncthreads();

        float acc[4][4] = {};
#pragma unroll 8
        for (int h = 0; h < 64; h++) {
            float4 p = *(const float4*)(Pt + h * 68 + 4 * tb);
            float4 q = *(const float4*)(Qt + h * 68 + 4 * tn);
            float w = ws[h];
            float pp[4] = {p.x, p.y, p.z, p.w}, qq[4] = {q.x, q.y, q.z, q.w};
#pragma unroll
            for (int i = 0; i < 4; i++)
#pragma unroll
                for (int j = 0; j < 4; j++)
                    acc[i][j] = fmaf(fmaxf(pp[i] + qq[j], 0.f), w, acc[i][j]);
        }
        __syncthreads();

        float* PB = Qt;
        float alpha[4];
#pragma unroll
        for (int i = 0; i < 4; i++) {
#pragma unroll
            for (int j = 0; j < 4; j++)
                acc[i][j] = (acc[i][j] + bias2) * msk[4 * tn + j];
            float mx = fmaxf(fmaxf(acc[i][0], acc[i][1]), fmaxf(acc[i][2], acc[i][3]));
#pragma unroll
            for (int o = 1; o < 16; o <<= 1) mx = fmaxf(mx, __shfl_xor_sync(0xffffffffu, mx, o));
            float mnew = fmaxf(m_run[i], mx);
            alpha[i] = __expf(m_run[i] - mnew);
            m_run[i] = mnew;
            float4 pv;
            pv.x = __expf(acc[i][0] - mnew);
            pv.y = __expf(acc[i][1] - mnew);
            pv.z = __expf(acc[i][2] - mnew);
            pv.w = __expf(acc[i][3] - mnew);
            *(float4*)(PB + (4 * tb + i) * 68 + 4 * tn) = pv;
            float s = pv.x + pv.y + pv.z + pv.w;
#pragma unroll
            for (int o = 1; o < 16; o <<= 1) s += __shfl_xor_sync(0xffffffffu, s, o);
            l_run[i] = l_run[i] * alpha[i] + s;
        }
        __syncthreads();

#pragma unroll
        for (int i = 0; i < 4; i++)
#pragma unroll
            for (int j = 0; j < 4; j++) ctxa[i][j] *= alpha[i];
#pragma unroll 2
        for (int n = 0; n < 64; n++) {
            float4 nev = *(const float4*)(NE + n * 64 + 4 * tn);
            float nn[4] = {nev.x, nev.y, nev.z, nev.w};
#pragma unroll
            for (int i = 0; i < 4; i++) {
                float pbv = PB[(4 * tb + i) * 68 + n];
#pragma unroll
                for (int j = 0; j < 4; j++)
                    ctxa[i][j] = fmaf(pbv, nn[j], ctxa[i][j]);
            }
        }
    }

    float* ctxc = ctx + ((long)c * 1024 + b0) * 64;
#pragma unroll
    for (int i = 0; i < 4; i++) {
        float inv = 1.f / l_run[i];
        float4 v = make_float4(ctxa[i][0] * inv, ctxa[i][1] * inv, ctxa[i][2] * inv, ctxa[i][3] * inv);
        *(float4*)(ctxc + (long)(4 * tb + i) * 64 + 4 * tn) = v;
    }
}

__global__ void gru_kernel(const float* __restrict__ gi_all, const float* __restrict__ pregh,
                           const float* __restrict__ s_in, float* __restrict__ s_out) {
    long idx = (long)blockIdx.x * blockDim.x + threadIdx.x;
    if (idx >= (long)CC * NN * HH) return;
    int c = (int)(idx >> 16), r = (int)(idx & 65535), n = r >> 6, h = r & 63;
    const float* gi = gi_all + ((long)c * 1024 + n) * 192;
    const float* gh = pregh + ((long)c * 1024 + n) * 256 + 64;
    float rr = 1.f / (1.f + expf(-(gi[h] + gh[h])));
    float zz = 1.f / (1.f + expf(-(gi[64 + h] + gh[64 + h])));
    float cand = tanhf(gi[128 + h] + rr * gh[128 + h]);
    s_out[idx] = (1.f - zz) * cand + zz * s_in[idx];
}

__global__ void transpose_kernel(const float* __restrict__ s, float* __restrict__ out) {
    long idx = (long)blockIdx.x * blockDim.x + threadIdx.x;
    if (idx >= (long)CC * NN * HH) return;
    int c = (int)(idx >> 16), n = (int)((idx >> 6) & 1023), h = (int)(idx & 63);
    out[(long)n * (CC * HH) + c * HH + h] = s[idx];
}

__global__ void reduce_chains_kernel(const float* __restrict__ part, const float* __restrict__ bias,
                                     float* __restrict__ out) {
    int idx = blockIdx.x * blockDim.x + threadIdx.x;
    if (idx >= NN * HH) return;
    float s = bias[idx & 63];
#pragma unroll
    for (int c = 0; c < CC; c++) s += part[(long)c * NN * HH + idx];
    out[idx] = fmaxf(s, 0.f);
}

__global__ void attnpred_kernel(const float* __restrict__ final_, const float* __restrict__ stacked,
                                const float* __restrict__ Wp, const float* __restrict__ bp,
                                float* __restrict__ attn, float* __restrict__ pred) {
    int warp = threadIdx.x >> 5, lane = threadIdx.x & 31;
    int n = blockIdx.x * 4 + warp;
    if (n >= NN) return;
    const float* f = final_ + (long)n * 64;
    float f0 = f[lane], f1 = f[lane + 32];
    float lg[CC];
#pragma unroll
    for (int c = 0; c < CC; c++) {
        const float* st = stacked + (long)n * (CC * HH) + c * HH;
        float v = f0 * st[lane] + f1 * st[lane + 32];
#pragma unroll
        for (int o = 16; o; o >>= 1) v += __shfl_xor_sync(0xffffffffu, v, o);
        lg[c] = v;
    }
    float p = f0 * Wp[lane] + f1 * Wp[lane + 32];
#pragma unroll
    for (int o = 16; o; o >>= 1) p += __shfl_xor_sync(0xffffffffu, p, o);
    float mx = lg[0];
#pragma unroll
    for (int c = 1; c < CC; c++) mx = fmaxf(mx, lg[c]);
    float e[CC], s = 0.f;
#pragma unroll
    for (int c = 0; c < CC; c++) { e[c] = expf(lg[c] - mx); s += e[c]; }
    if (lane == 0) {
        float inv = 1.f / s;
#pragma unroll
        for (int c = 0; c < CC; c++) attn[(long)n * CC + c] = e[c] * inv;
        pred[n] = p + bp[0];
    }
}

extern "C" void kernel_launch(void* const* d_in, const int* in_sizes, int n_in,
                              void* d_out, int out_size) {
    const float* node_feats = (const float*)d_in[0];
    const int*   edges      = (const int*)d_in[1];
    const float* Wt1  = (const float*)d_in[2];
    const float* bt1  = (const float*)d_in[3];
    const float* Wt2  = (const float*)d_in[4];
    const float* bt2  = (const float*)d_in[5];
    const float* Wci  = (const float*)d_in[6];
    const float* bci  = (const float*)d_in[7];
    const float* Wa1  = (const float*)d_in[8];
    const float* ba1  = (const float*)d_in[9];
    const float* Wa2  = (const float*)d_in[10];
    const float* ba2  = (const float*)d_in[11];
    const float* Wih  = (const float*)d_in[12];
    const float* Whh  = (const float*)d_in[13];
    const float* bih  = (const float*)d_in[14];
    const float* bhh  = (const float*)d_in[15];
    const float* Wag1 = (const float*)d_in[16];
    const float* bag1 = (const float*)d_in[17];
    const float* Wag2 = (const float*)d_in[18];
    const float* bag2 = (const float*)d_in[19];
    const float* Wp   = (const float*)d_in[20];
    const float* bp   = (const float*)d_in[21];
    float* out = (float*)d_out;

    float* S = nullptr;
    cudaGetSymbolAddress((void**)&S, g_scratch);
    float* g_t1 = S + O_T1;   float* g_ne = S + O_NE;   float* g_np = S + O_NP;
    float* g_s = S + O_S;     float* g_pregh = S + O_PREGH;
    float* g_ctx = S + O_CTX; float* g_gi = S + O_GI;
    float* g_Wp1 = S + O_WP1; float* g_bp1 = S + O_BP1;
    float* g_WihT = S + O_WIHT; float* g_mask = S + O_MASK;

    cudaFuncSetAttribute(attn_step_kernel, cudaFuncAttributeMaxDynamicSharedMemorySize, SMEM_ATTN);

    const long CH = (long)CC * NN * HH;
    int E = in_sizes[1] / 2;

    zero_kernel<<<4, 256>>>(g_mask, NN);
    scatter_mask_kernel<<<(E + 255) / 256, 256>>>(edges, E, g_mask);

    gemm_tiled<1><<<dim3(1, 16, 1), 256>>>(node_feats, 0, DD, Wt1, 0, HH, bt1, 0, g_t1, 0, HH, DD);
    gemm_tiled<1><<<dim3(1, 16, 1), 256>>>(g_t1, 0, HH, Wt2, 0, HH, bt2, 0, g_ne, 0, HH, HH);

    pack_kernel<<<256, 256>>>(Wa1, Whh, ba1, bhh, Wih, g_Wp1, g_bp1, g_WihT);

    gemm_tiled<0><<<dim3(1, 16, CC), 256>>>(g_ne, 0, HH, Wci, 64, CC * HH, bci, 64,
                                            g_s, (long)NN * HH, HH, HH);
    gemm_tiled<0><<<dim3(1, 16, CC), 256>>>(g_ne, 0, HH, Wa1 + 64 * 64, 128 * 64, HH, nullptr, 0,
                                            g_np, (long)NN * HH, HH, HH);

    int cur = 0;
    for (int step = 0; step < LL; step++) {
        float* s_in = g_s + (long)cur * CH;
        float* s_out = g_s + (long)(1 - cur) * CH;
        gemm_tiled<0><<<dim3(4, 16, CC), 256>>>(s_in, (long)NN * HH, HH,
                                                g_Wp1, 64 * 256, 256, g_bp1, 256,
                                                g_pregh, (long)NN * 256, 256, HH);
        attn_step_kernel<<<dim3(16, CC), 256, SMEM_ATTN>>>(g_pregh, g_np, g_ne, Wa2, ba2, g_mask, g_ctx);
        gemm_tiled<0><<<dim3(3, 16, CC), 256>>>(g_ctx, (long)NN * HH, HH,
                                                g_WihT, 64 * 192, 192, bih, 192,
                                                g_gi, (long)NN * 192, 192, HH);
        gru_kernel<<<(int)(CH / 256), 256>>>(g_gi, g_pregh, s_in, s_out);
        cur ^= 1;
    }
    float* s_fin = g_s + (long)cur * CH;

    transpose_kernel<<<(int)(CH / 256), 256>>>(s_fin, out + OUT_STACKED);

    // concat @ Wag1 as 20 per-chain partials (into g_ctx), then reduce + relu -> g_t1
    gemm_tiled<0><<<dim3(1, 16, CC), 256>>>(s_fin, (long)NN * HH, HH,
                                            Wag1, 64 * 64, HH, nullptr, 0,
                                            g_ctx, (long)NN * HH, HH, HH);
    reduce_chains_kernel<<<NN * HH / 256, 256>>>(g_ctx, bag1, g_t1);

    // final = h1 @ Wag2 + bag2  -> out
    gemm_tiled<0><<<dim3(1, 16, 1), 256>>>(g_t1, 0, HH, Wag2, 0, HH, bag2, 0,
                                           out + OUT_FINAL, 0, HH, HH);

    attnpred_kernel<<<NN / 4, 128>>>(out + OUT_FINAL, out + OUT_STACKED, Wp, bp,
                                     out + OUT_ATTN, out + OUT_PRED);
}

// round 6
// speedup vs baseline: 1.9273x; 1.9273x over previous
#include <cuda_runtime.h>
#include <math.h>

typedef unsigned long long u64;

__device__ __forceinline__ u64 pk(float a, float b) {
    u64 d; asm("mov.b64 %0, {%1,%2};" : "=l"(d) : "f"(a), "f"(b)); return d;
}
__device__ __forceinline__ void upk(u64 d, float& a, float& b) {
    asm("mov.b64 {%0,%1}, %2;" : "=f"(a), "=f"(b) : "l"(d));
}
__device__ __forceinline__ u64 fma2(u64 a, u64 b, u64 c) {
    u64 d; asm("fma.rn.f32x2 %0, %1, %2, %3;" : "=l"(d) : "l"(a), "l"(b), "l"(c)); return d;
}
__device__ __forceinline__ u64 add2(u64 a, u64 b) {
    u64 d; asm("add.rn.f32x2 %0, %1, %2;" : "=l"(d) : "l"(a), "l"(b)); return d;
}
__device__ __forceinline__ u64 mul2(u64 a, u64 b) {
    u64 d; asm("mul.rn.f32x2 %0, %1, %2;" : "=l"(d) : "l"(a), "l"(b)); return d;
}

constexpr int NN = 1024, DD = 256, HH = 64, CC = 20, LL = 3;

constexpr long OUT_STACKED = 0;
constexpr long OUT_FINAL   = (long)NN * CC * HH;
constexpr long OUT_ATTN    = OUT_FINAL + (long)NN * HH;
constexpr long OUT_PRED    = OUT_ATTN + (long)NN * CC;

constexpr long O_T1    = 0;
constexpr long O_NE    = O_T1 + (long)NN * HH;
constexpr long O_NP    = O_NE + (long)NN * HH;
constexpr long O_S     = O_NP + (long)CC * NN * HH;
constexpr long O_PREGH = O_S + 2L * CC * NN * HH;
constexpr long O_CTX   = O_PREGH + (long)CC * NN * 256;
constexpr long O_GI    = O_CTX + (long)CC * NN * HH;
constexpr long O_WP1   = O_GI + (long)CC * NN * 192;
constexpr long O_BP1   = O_WP1 + (long)CC * 64 * 256;
constexpr long O_WIHT  = O_BP1 + (long)CC * 256;
constexpr long O_MASK  = O_WIHT + (long)CC * 64 * 192;
constexpr long O_NPT   = O_MASK + NN;
constexpr long SCRATCH = O_NPT + (long)CC * 64 * 1024;

__device__ float g_scratch[SCRATCH];

__global__ void zero_kernel(float* __restrict__ p, int n) {
    for (int i = blockIdx.x * blockDim.x + threadIdx.x; i < n; i += gridDim.x * blockDim.x)
        p[i] = 0.f;
}

__global__ void scatter_mask_kernel(const int* __restrict__ edges, int E, float* __restrict__ mask) {
    int i = blockIdx.x * blockDim.x + threadIdx.x;
    if (i < E) mask[edges[2 * i + 1]] = 1.0f;
}

__global__ void pack_kernel(const float* __restrict__ Wa1, const float* __restrict__ Whh,
                            const float* __restrict__ ba1, const float* __restrict__ bhh,
                            const float* __restrict__ Wih,
                            float* __restrict__ Wp1, float* __restrict__ bp1,
                            float* __restrict__ WihT) {
    int stride = gridDim.x * blockDim.x;
    int idx = blockIdx.x * blockDim.x + threadIdx.x;
    for (int t = idx; t < CC * 64 * 256; t += stride) {
        int c = t / (64 * 256), r = t % (64 * 256), k = r / 256, j = r % 256;
        Wp1[t] = (j < 64) ? Wa1[((long)c * 128 + k) * 64 + j]
                          : Whh[((long)c * 192 + (j - 64)) * 64 + k];
    }
    for (int t = idx; t < CC * 64 * 192; t += stride) {
        int c = t / (64 * 192), r = t % (64 * 192), k = r / 192, j = r % 192;
        WihT[t] = Wih[((long)c * 192 + j) * 64 + k];
    }
    for (int t = idx; t < CC * 256; t += stride) {
        int c = t / 256, j = t % 256;
        bp1[t] = (j < 64) ? ba1[c * 64 + j] : bhh[c * 192 + (j - 64)];
    }
}

// np[c][n][h] -> npT[c][h][n]
__global__ void transpose_np_kernel(const float* __restrict__ in, float* __restrict__ out) {
    long idx = (long)blockIdx.x * blockDim.x + threadIdx.x;
    if (idx >= (long)CC * NN * HH) return;
    int c = (int)(idx >> 16), h = (int)((idx >> 10) & 63), n = (int)(idx & 1023);
    out[idx] = in[(long)c * 65536 + (long)n * 64 + h];
}

// Out[c] = act(A[c] @ W[c] + bias). 64x64 block tile, 4x4/thread, BK=32, f32x2 inner.
template<int ACT>
__global__ void __launch_bounds__(256) gemm_tiled(
    const float* __restrict__ A, long aCS, int lda,
    const float* __restrict__ W, long wCS, int ldw,
    const float* __restrict__ Bv, long bCS,
    float* __restrict__ Out, long oCS, int ldo, int K) {
    __shared__ float As[32 * 68];
    __shared__ float Bs[32 * 64];
    const int c = blockIdx.z;
    A += (long)c * aCS; W += (long)c * wCS; Out += (long)c * oCS;
    if (Bv) Bv += (long)c * bCS;
    const int row0 = blockIdx.y * 64, col0 = blockIdx.x * 64;
    const int tid = threadIdx.x, tb = tid >> 4, tn = tid & 15;
    u64 acc2[4][2] = {};
    for (int k0 = 0; k0 < K; k0 += 32) {
#pragma unroll
        for (int r = 0; r < 2; r++) {
            int idx = tid + r * 256;
            int n = idx >> 3, kg = idx & 7;
            float4 av = *(const float4*)(A + (long)(row0 + n) * lda + k0 + 4 * kg);
            As[(4 * kg + 0) * 68 + n] = av.x;
            As[(4 * kg + 1) * 68 + n] = av.y;
            As[(4 * kg + 2) * 68 + n] = av.z;
            As[(4 * kg + 3) * 68 + n] = av.w;
            int kk = idx >> 4, j4 = idx & 15;
            *(float4*)(Bs + kk * 64 + 4 * j4) = *(const float4*)(W + (long)(k0 + kk) * ldw + col0 + 4 * j4);
        }
        __syncthreads();
#pragma unroll 8
        for (int k = 0; k < 32; k++) {
            float4 a = *(const float4*)(As + k * 68 + 4 * tb);
            ulonglong2 b2 = *(const ulonglong2*)(Bs + k * 64 + 4 * tn);
            float aa[4] = {a.x, a.y, a.z, a.w};
#pragma unroll
            for (int i = 0; i < 4; i++) {
                u64 ai2 = pk(aa[i], aa[i]);
                acc2[i][0] = fma2(ai2, b2.x, acc2[i][0]);
                acc2[i][1] = fma2(ai2, b2.y, acc2[i][1]);
            }
        }
        __syncthreads();
    }
    float bb[4] = {0.f, 0.f, 0.f, 0.f};
    if (Bv) {
        bb[0] = Bv[col0 + 4 * tn]; bb[1] = Bv[col0 + 4 * tn + 1];
        bb[2] = Bv[col0 + 4 * tn + 2]; bb[3] = Bv[col0 + 4 * tn + 3];
    }
#pragma unroll
    for (int i = 0; i < 4; i++) {
        float o_[4];
        upk(acc2[i][0], o_[0], o_[1]);
        upk(acc2[i][1], o_[2], o_[3]);
        float t0 = o_[0] + bb[0], t1 = o_[1] + bb[1], t2 = o_[2] + bb[2], t3 = o_[3] + bb[3];
        if (ACT == 1) { t0 = fmaxf(t0, 0.f); t1 = fmaxf(t1, 0.f); t2 = fmaxf(t2, 0.f); t3 = fmaxf(t3, 0.f); }
        *(float4*)(Out + (long)(row0 + 4 * tb + i) * ldo + col0 + 4 * tn) = make_float4(t0, t1, t2, t3);
    }
}

// Fused attention step, b-tile 32, 128 threads, packed f32x2 math.
__global__ void __launch_bounds__(128) attn_step_kernel(
    const float* __restrict__ pregh, const float* __restrict__ npT,
    const float* __restrict__ ne, const float* __restrict__ Wa2,
    const float* __restrict__ ba2, const float* __restrict__ mask,
    float* __restrict__ ctx) {
    __shared__ float Pt[64 * 36];   // [h][32b + pad]
    __shared__ float Qt[64 * 68];   // [h][64n + pad]; reused as PB[32b][68]
    __shared__ float NE[64 * 64];   // [n][h]
    __shared__ float msk[64];
    __shared__ u64 ws2[64];

    const int c = blockIdx.y, b0 = blockIdx.x * 32;
    const int tid = threadIdx.x, tb = tid >> 4, tn = tid & 15;

    if (tid < 64) { float w = Wa2[c * 64 + tid]; ws2[tid] = pk(w, w); }
    const float bias2 = ba2[c];

    const float* preB = pregh + ((long)c * 1024 + b0) * 256;
#pragma unroll
    for (int r = 0; r < 4; r++) {
        int idx = tid + r * 128, h = idx & 63, b4 = idx >> 6;
        float4 v;
        v.x = preB[(long)(4 * b4 + 0) * 256 + h];
        v.y = preB[(long)(4 * b4 + 1) * 256 + h];
        v.z = preB[(long)(4 * b4 + 2) * 256 + h];
        v.w = preB[(long)(4 * b4 + 3) * 256 + h];
        *(float4*)(Pt + h * 36 + 4 * b4) = v;
    }

    float m_run[4], l_run[4];
    u64 ctxa2[4][2] = {};
#pragma unroll
    for (int i = 0; i < 4; i++) { m_run[i] = -1e30f; l_run[i] = 0.f; }

    const float* npc = npT + (long)c * 64 * 1024;

    for (int nt = 0; nt < 1024; nt += 64) {
        __syncthreads();
#pragma unroll
        for (int r = 0; r < 8; r++) {
            int idx = tid + r * 128;
            int h = idx >> 4, q4 = idx & 15;
            *(float4*)(Qt + h * 68 + 4 * q4) = *(const float4*)(npc + (long)h * 1024 + nt + 4 * q4);
            *(float4*)(NE + h * 64 + 4 * q4) = *(const float4*)(ne + (long)(nt + h) * 64 + 4 * q4);
        }
        if (tid < 64) msk[tid] = mask[nt + tid];
        __syncthreads();

        u64 acc2[4][2] = {};
#pragma unroll 4
        for (int h = 0; h < 64; h++) {
            float4 p = *(const float4*)(Pt + h * 36 + 4 * tb);
            ulonglong2 q = *(const ulonglong2*)(Qt + h * 68 + 4 * tn);
            u64 w2 = ws2[h];
            float pp[4] = {p.x, p.y, p.z, p.w};
#pragma unroll
            for (int i = 0; i < 4; i++) {
                u64 pi2 = pk(pp[i], pp[i]);
                u64 t0 = add2(pi2, q.x);
                u64 t1 = add2(pi2, q.y);
                float a0, a1, b0f, b1f;
                upk(t0, a0, a1); upk(t1, b0f, b1f);
                a0 = fmaxf(a0, 0.f); a1 = fmaxf(a1, 0.f);
                b0f = fmaxf(b0f, 0.f); b1f = fmaxf(b1f, 0.f);
                acc2[i][0] = fma2(pk(a0, a1), w2, acc2[i][0]);
                acc2[i][1] = fma2(pk(b0f, b1f), w2, acc2[i][1]);
            }
        }
        __syncthreads();  // Qt reads done before PB overwrite

        float* PB = Qt;
        float4 msk4 = *(const float4*)(msk + 4 * tn);
        float mk[4] = {msk4.x, msk4.y, msk4.z, msk4.w};
        float alpha[4];
#pragma unroll
        for (int i = 0; i < 4; i++) {
            float sc[4];
            upk(acc2[i][0], sc[0], sc[1]);
            upk(acc2[i][1], sc[2], sc[3]);
#pragma unroll
            for (int j = 0; j < 4; j++) sc[j] = (sc[j] + bias2) * mk[j];
            float mx = fmaxf(fmaxf(sc[0], sc[1]), fmaxf(sc[2], sc[3]));
#pragma unroll
            for (int o = 1; o < 16; o <<= 1) mx = fmaxf(mx, __shfl_xor_sync(0xffffffffu, mx, o));
            float mnew = fmaxf(m_run[i], mx);
            alpha[i] = __expf(m_run[i] - mnew);
            m_run[i] = mnew;
            float4 pv;
            pv.x = __expf(sc[0] - mnew);
            pv.y = __expf(sc[1] - mnew);
            pv.z = __expf(sc[2] - mnew);
            pv.w = __expf(sc[3] - mnew);
            *(float4*)(PB + (4 * tb + i) * 68 + 4 * tn) = pv;
            float s = pv.x + pv.y + pv.z + pv.w;
#pragma unroll
            for (int o = 1; o < 16; o <<= 1) s += __shfl_xor_sync(0xffffffffu, s, o);
            l_run[i] = l_run[i] * alpha[i] + s;
        }
        __syncthreads();  // PB visible

#pragma unroll
        for (int i = 0; i < 4; i++) {
            u64 al2 = pk(alpha[i], alpha[i]);
            ctxa2[i][0] = mul2(ctxa2[i][0], al2);
            ctxa2[i][1] = mul2(ctxa2[i][1], al2);
        }
        for (int n0 = 0; n0 < 64; n0 += 4) {
            float pbA[4][4];
#pragma unroll
            for (int i = 0; i < 4; i++) {
                float4 pv = *(const float4*)(PB + (4 * tb + i) * 68 + n0);
                pbA[i][0] = pv.x; pbA[i][1] = pv.y; pbA[i][2] = pv.z; pbA[i][3] = pv.w;
            }
#pragma unroll
            for (int k = 0; k < 4; k++) {
                ulonglong2 ne2 = *(const ulonglong2*)(NE + (n0 + k) * 64 + 4 * tn);
#pragma unroll
                for (int i = 0; i < 4; i++) {
                    u64 p2 = pk(pbA[i][k], pbA[i][k]);
                    ctxa2[i][0] = fma2(p2, ne2.x, ctxa2[i][0]);
                    ctxa2[i][1] = fma2(p2, ne2.y, ctxa2[i][1]);
                }
            }
        }
    }

    float* ctxc = ctx + ((long)c * 1024 + b0) * 64;
#pragma unroll
    for (int i = 0; i < 4; i++) {
        float inv = 1.f / l_run[i];
        float o_[4];
        upk(ctxa2[i][0], o_[0], o_[1]);
        upk(ctxa2[i][1], o_[2], o_[3]);
        *(float4*)(ctxc + (long)(4 * tb + i) * 64 + 4 * tn) =
            make_float4(o_[0] * inv, o_[1] * inv, o_[2] * inv, o_[3] * inv);
    }
}

__global__ void gru_kernel(const float* __restrict__ gi_all, const float* __restrict__ pregh,
                           const float* __restrict__ s_in, float* __restrict__ s_out) {
    long idx = (long)blockIdx.x * blockDim.x + threadIdx.x;
    if (idx >= (long)CC * NN * HH) return;
    int c = (int)(idx >> 16), r = (int)(idx & 65535), n = r >> 6, h = r & 63;
    const float* gi = gi_all + ((long)c * 1024 + n) * 192;
    const float* gh = pregh + ((long)c * 1024 + n) * 256 + 64;
    float rr = 1.f / (1.f + expf(-(gi[h] + gh[h])));
    float zz = 1.f / (1.f + expf(-(gi[64 + h] + gh[64 + h])));
    float cand = tanhf(gi[128 + h] + rr * gh[128 + h]);
    s_out[idx] = (1.f - zz) * cand + zz * s_in[idx];
}

__global__ void transpose_kernel(const float* __restrict__ s, float* __restrict__ out) {
    long idx = (long)blockIdx.x * blockDim.x + threadIdx.x;
    if (idx >= (long)CC * NN * HH) return;
    int c = (int)(idx >> 16), n = (int)((idx >> 6) & 1023), h = (int)(idx & 63);
    out[(long)n * (CC * HH) + c * HH + h] = s[idx];
}

__global__ void reduce_chains_kernel(const float* __restrict__ part, const float* __restrict__ bias,
                                     float* __restrict__ out) {
    int idx = blockIdx.x * blockDim.x + threadIdx.x;
    if (idx >= NN * HH) return;
    float s = bias[idx & 63];
#pragma unroll
    for (int c = 0; c < CC; c++) s += part[(long)c * NN * HH + idx];
    out[idx] = fmaxf(s, 0.f);
}

__global__ void attnpred_kernel(const float* __restrict__ final_, const float* __restrict__ stacked,
                                const float* __restrict__ Wp, const float* __restrict__ bp,
                                float* __restrict__ attn, float* __restrict__ pred) {
    int warp = threadIdx.x >> 5, lane = threadIdx.x & 31;
    int n = blockIdx.x * 4 + warp;
    if (n >= NN) return;
    const float* f = final_ + (long)n * 64;
    float f0 = f[lane], f1 = f[lane + 32];
    float lg[CC];
#pragma unroll
    for (int c = 0; c < CC; c++) {
        const float* st = stacked + (long)n * (CC * HH) + c * HH;
        float v = f0 * st[lane] + f1 * st[lane + 32];
#pragma unroll
        for (int o = 16; o; o >>= 1) v += __shfl_xor_sync(0xffffffffu, v, o);
        lg[c] = v;
    }
    float p = f0 * Wp[lane] + f1 * Wp[lane + 32];
#pragma unroll
    for (int o = 16; o; o >>= 1) p += __shfl_xor_sync(0xffffffffu, p, o);
    float mx = lg[0];
#pragma unroll
    for (int c = 1; c < CC; c++) mx = fmaxf(mx, lg[c]);
    float e[CC], s = 0.f;
#pragma unroll
    for (int c = 0; c < CC; c++) { e[c] = expf(lg[c] - mx); s += e[c]; }
    if (lane == 0) {
        float inv = 1.f / s;
#pragma unroll
        for (int c = 0; c < CC; c++) attn[(long)n * CC + c] = e[c] * inv;
        pred[n] = p + bp[0];
    }
}

extern "C" void kernel_launch(void* const* d_in, const int* in_sizes, int n_in,
                              void* d_out, int out_size) {
    const float* node_feats = (const float*)d_in[0];
    const int*   edges      = (const int*)d_in[1];
    const float* Wt1  = (const float*)d_in[2];
    const float* bt1  = (const float*)d_in[3];
    const float* Wt2  = (const float*)d_in[4];
    const float* bt2  = (const float*)d_in[5];
    const float* Wci  = (const float*)d_in[6];
    const float* bci  = (const float*)d_in[7];
    const float* Wa1  = (const float*)d_in[8];
    const float* ba1  = (const float*)d_in[9];
    const float* Wa2  = (const float*)d_in[10];
    const float* ba2  = (const float*)d_in[11];
    const float* Wih  = (const float*)d_in[12];
    const float* Whh  = (const float*)d_in[13];
    const float* bih  = (const float*)d_in[14];
    const float* bhh  = (const float*)d_in[15];
    const float* Wag1 = (const float*)d_in[16];
    const float* bag1 = (const float*)d_in[17];
    const float* Wag2 = (const float*)d_in[18];
    const float* bag2 = (const float*)d_in[19];
    const float* Wp   = (const float*)d_in[20];
    const float* bp   = (const float*)d_in[21];
    float* out = (float*)d_out;

    float* S = nullptr;
    cudaGetSymbolAddress((void**)&S, g_scratch);
    float* g_t1 = S + O_T1;   float* g_ne = S + O_NE;   float* g_np = S + O_NP;
    float* g_s = S + O_S;     float* g_pregh = S + O_PREGH;
    float* g_ctx = S + O_CTX; float* g_gi = S + O_GI;
    float* g_Wp1 = S + O_WP1; float* g_bp1 = S + O_BP1;
    float* g_WihT = S + O_WIHT; float* g_mask = S + O_MASK;
    float* g_npT = S + O_NPT;

    const long CH = (long)CC * NN * HH;
    int E = in_sizes[1] / 2;

    zero_kernel<<<4, 256>>>(g_mask, NN);
    scatter_mask_kernel<<<(E + 255) / 256, 256>>>(edges, E, g_mask);

    gemm_tiled<1><<<dim3(1, 16, 1), 256>>>(node_feats, 0, DD, Wt1, 0, HH, bt1, 0, g_t1, 0, HH, DD);
    gemm_tiled<1><<<dim3(1, 16, 1), 256>>>(g_t1, 0, HH, Wt2, 0, HH, bt2, 0, g_ne, 0, HH, HH);

    pack_kernel<<<256, 256>>>(Wa1, Whh, ba1, bhh, Wih, g_Wp1, g_bp1, g_WihT);

    gemm_tiled<0><<<dim3(1, 16, CC), 256>>>(g_ne, 0, HH, Wci, 64, CC * HH, bci, 64,
                                            g_s, (long)NN * HH, HH, HH);
    gemm_tiled<0><<<dim3(1, 16, CC), 256>>>(g_ne, 0, HH, Wa1 + 64 * 64, 128 * 64, HH, nullptr, 0,
                                            g_np, (long)NN * HH, HH, HH);
    transpose_np_kernel<<<(int)(CH / 256), 256>>>(g_np, g_npT);

    int cur = 0;
    for (int step = 0; step < LL; step++) {
        float* s_in = g_s + (long)cur * CH;
        float* s_out = g_s + (long)(1 - cur) * CH;
        gemm_tiled<0><<<dim3(4, 16, CC), 256>>>(s_in, (long)NN * HH, HH,
                                                g_Wp1, 64 * 256, 256, g_bp1, 256,
                                                g_pregh, (long)NN * 256, 256, HH);
        attn_step_kernel<<<dim3(32, CC), 128>>>(g_pregh, g_npT, g_ne, Wa2, ba2, g_mask, g_ctx);
        gemm_tiled<0><<<dim3(3, 16, CC), 256>>>(g_ctx, (long)NN * HH, HH,
                                                g_WihT, 64 * 192, 192, bih, 192,
                                                g_gi, (long)NN * 192, 192, HH);
        gru_kernel<<<(int)(CH / 256), 256>>>(g_gi, g_pregh, s_in, s_out);
        cur ^= 1;
    }
    float* s_fin = g_s + (long)cur * CH;

    transpose_kernel<<<(int)(CH / 256), 256>>>(s_fin, out + OUT_STACKED);

    gemm_tiled<0><<<dim3(1, 16, CC), 256>>>(s_fin, (long)NN * HH, HH,
                                            Wag1, 64 * 64, HH, nullptr, 0,
                                            g_ctx, (long)NN * HH, HH, HH);
    reduce_chains_kernel<<<NN * HH / 256, 256>>>(g_ctx, bag1, g_t1);

    gemm_tiled<0><<<dim3(1, 16, 1), 256>>>(g_t1, 0, HH, Wag2, 0, HH, bag2, 0,
                                           out + OUT_FINAL, 0, HH, HH);

    attnpred_kernel<<<NN / 4, 128>>>(out + OUT_FINAL, out + OUT_STACKED, Wp, bp,
                                     out + OUT_ATTN, out + OUT_PRED);
}

// round 16
// speedup vs baseline: 1.9477x; 1.0106x over previous
#include <cuda_runtime.h>
#include <math.h>

typedef unsigned long long u64;

__device__ __forceinline__ u64 pk(float a, float b) {
    u64 d; asm("mov.b64 %0, {%1,%2};" : "=l"(d) : "f"(a), "f"(b)); return d;
}
__device__ __forceinline__ void upk(u64 d, float& a, float& b) {
    asm("mov.b64 {%0,%1}, %2;" : "=f"(a), "=f"(b) : "l"(d));
}
__device__ __forceinline__ u64 fma2(u64 a, u64 b, u64 c) {
    u64 d; asm("fma.rn.f32x2 %0, %1, %2, %3;" : "=l"(d) : "l"(a), "l"(b), "l"(c)); return d;
}
__device__ __forceinline__ u64 add2(u64 a, u64 b) {
    u64 d; asm("add.rn.f32x2 %0, %1, %2;" : "=l"(d) : "l"(a), "l"(b)); return d;
}
__device__ __forceinline__ u64 mul2(u64 a, u64 b) {
    u64 d; asm("mul.rn.f32x2 %0, %1, %2;" : "=l"(d) : "l"(a), "l"(b)); return d;
}

constexpr int NN = 1024, DD = 256, HH = 64, CC = 20, LL = 3;

constexpr long OUT_STACKED = 0;
constexpr long OUT_FINAL   = (long)NN * CC * HH;
constexpr long OUT_ATTN    = OUT_FINAL + (long)NN * HH;
constexpr long OUT_PRED    = OUT_ATTN + (long)NN * CC;

constexpr long O_T1    = 0;
constexpr long O_NE    = O_T1 + (long)NN * HH;
constexpr long O_NP    = O_NE + (long)NN * HH;
constexpr long O_S     = O_NP + (long)CC * NN * HH;
constexpr long O_CTX   = O_S + 2L * CC * NN * HH;
constexpr long O_WIHT  = O_CTX + (long)CC * NN * HH;
constexpr long O_WHHT  = O_WIHT + (long)CC * 64 * 192;
constexpr long O_MASK  = O_WHHT + (long)CC * 64 * 192;
constexpr long O_NPT   = O_MASK + NN;
constexpr long SCRATCH = O_NPT + (long)CC * 64 * 1024;

__device__ float g_scratch[SCRATCH];

__global__ void zero_kernel(float* __restrict__ p, int n) {
    for (int i = blockIdx.x * blockDim.x + threadIdx.x; i < n; i += gridDim.x * blockDim.x)
        p[i] = 0.f;
}

__global__ void scatter_mask_kernel(const int* __restrict__ edges, int E, float* __restrict__ mask) {
    int i = blockIdx.x * blockDim.x + threadIdx.x;
    if (i < E) mask[edges[2 * i + 1]] = 1.0f;
}

__global__ void pack_kernel(const float* __restrict__ Wih, const float* __restrict__ Whh,
                            float* __restrict__ WihT, float* __restrict__ WhhT) {
    int stride = gridDim.x * blockDim.x;
    int idx = blockIdx.x * blockDim.x + threadIdx.x;
    for (int t = idx; t < CC * 64 * 192; t += stride) {
        int c = t / (64 * 192), r = t % (64 * 192), k = r / 192, j = r % 192;
        WihT[t] = Wih[((long)c * 192 + j) * 64 + k];
        WhhT[t] = Whh[((long)c * 192 + j) * 64 + k];
    }
}

__global__ void transpose_np_kernel(const float* __restrict__ in, float* __restrict__ out) {
    long idx = (long)blockIdx.x * blockDim.x + threadIdx.x;
    if (idx >= (long)CC * NN * HH) return;
    int c = (int)(idx >> 16), h = (int)((idx >> 10) & 63), n = (int)(idx & 1023);
    out[idx] = in[(long)c * 65536 + (long)n * 64 + h];
}

template<int ACT>
__global__ void __launch_bounds__(256) gemm_tiled(
    const float* __restrict__ A, long aCS, int lda,
    const float* __restrict__ W, long wCS, int ldw,
    const float* __restrict__ Bv, long bCS,
    float* __restrict__ Out, long oCS, int ldo, int K) {
    __shared__ float As[32 * 68];
    __shared__ float Bs[32 * 64];
    const int c = blockIdx.z;
    A += (long)c * aCS; W += (long)c * wCS; Out += (long)c * oCS;
    if (Bv) Bv += (long)c * bCS;
    const int row0 = blockIdx.y * 64, col0 = blockIdx.x * 64;
    const int tid = threadIdx.x, tb = tid >> 4, tn = tid & 15;
    u64 acc2[4][2] = {};
    for (int k0 = 0; k0 < K; k0 += 32) {
#pragma unroll
        for (int r = 0; r < 2; r++) {
            int idx = tid + r * 256;
            int n = idx >> 3, kg = idx & 7;
            float4 av = *(const float4*)(A + (long)(row0 + n) * lda + k0 + 4 * kg);
            As[(4 * kg + 0) * 68 + n] = av.x;
            As[(4 * kg + 1) * 68 + n] = av.y;
            As[(4 * kg + 2) * 68 + n] = av.z;
            As[(4 * kg + 3) * 68 + n] = av.w;
            int kk = idx >> 4, j4 = idx & 15;
            *(float4*)(Bs + kk * 64 + 4 * j4) = *(const float4*)(W + (long)(k0 + kk) * ldw + col0 + 4 * j4);
        }
        __syncthreads();
#pragma unroll 8
        for (int k = 0; k < 32; k++) {
            float4 a = *(const float4*)(As + k * 68 + 4 * tb);
            ulonglong2 b2 = *(const ulonglong2*)(Bs + k * 64 + 4 * tn);
            float aa[4] = {a.x, a.y, a.z, a.w};
#pragma unroll
            for (int i = 0; i < 4; i++) {
                u64 ai2 = pk(aa[i], aa[i]);
                acc2[i][0] = fma2(ai2, b2.x, acc2[i][0]);
                acc2[i][1] = fma2(ai2, b2.y, acc2[i][1]);
            }
        }
        __syncthreads();
    }
    float bb[4] = {0.f, 0.f, 0.f, 0.f};
    if (Bv) {
        bb[0] = Bv[col0 + 4 * tn]; bb[1] = Bv[col0 + 4 * tn + 1];
        bb[2] = Bv[col0 + 4 * tn + 2]; bb[3] = Bv[col0 + 4 * tn + 3];
    }
#pragma unroll
    for (int i = 0; i < 4; i++) {
        float o_[4];
        upk(acc2[i][0], o_[0], o_[1]);
        upk(acc2[i][1], o_[2], o_[3]);
        float t0 = o_[0] + bb[0], t1 = o_[1] + bb[1], t2 = o_[2] + bb[2], t3 = o_[3] + bb[3];
        if (ACT == 1) { t0 = fmaxf(t0, 0.f); t1 = fmaxf(t1, 0.f); t2 = fmaxf(t2, 0.f); t3 = fmaxf(t3, 0.f); }
        *(float4*)(Out + (long)(row0 + 4 * tb + i) * ldo + col0 + 4 * tn) = make_float4(t0, t1, t2, t3);
    }
}

// Fused attention step with in-kernel pre-GEMM prologue.
__global__ void __launch_bounds__(128) attn_step_kernel(
    const float* __restrict__ s_in, const float* __restrict__ npT,
    const float* __restrict__ ne, const float* __restrict__ Wa1,
    const float* __restrict__ ba1, const float* __restrict__ Wa2,
    const float* __restrict__ ba2, const float* __restrict__ mask,
    float* __restrict__ ctx) {
    __shared__ float Pt[64 * 36];
    __shared__ float Qt[64 * 68];
    __shared__ float NE[64 * 64];
    __shared__ float msk[64];
    __shared__ u64 ws2[64];

    const int c = blockIdx.y, b0 = blockIdx.x * 32;
    const int tid = threadIdx.x, tb = tid >> 4, tn = tid & 15;

    if (tid < 64) { float w = Wa2[c * 64 + tid]; ws2[tid] = pk(w, w); }
    const float bias2 = ba2[c];

    // Prologue: pre[32b][64h] -> Pt[h][b]
    {
        float* Wsh = Qt;
        float* Sk  = NE;
        const float* wsrc = Wa1 + (long)c * 128 * 64;
        const float* ssrc = s_in + ((long)c * 1024 + b0) * 64;
#pragma unroll
        for (int r = 0; r < 8; r++) {
            int idx = tid + r * 128;
            int k = idx >> 4, j4 = idx & 15;
            *(float4*)(Wsh + k * 68 + 4 * j4) = *(const float4*)(wsrc + k * 64 + 4 * j4);
        }
#pragma unroll
        for (int r = 0; r < 4; r++) {
            int idx = tid + r * 128;
            int b = idx >> 4, k4 = idx & 15;
            float4 v = *(const float4*)(ssrc + b * 64 + 4 * k4);
            Sk[(4 * k4 + 0) * 36 + b] = v.x;
            Sk[(4 * k4 + 1) * 36 + b] = v.y;
            Sk[(4 * k4 + 2) * 36 + b] = v.z;
            Sk[(4 * k4 + 3) * 36 + b] = v.w;
        }
        __syncthreads();
        u64 pacc[4][2] = {};
#pragma unroll 8
        for (int k = 0; k < 64; k++) {
            float4 s4 = *(const float4*)(Sk + k * 36 + 4 * tb);
            ulonglong2 w2 = *(const ulonglong2*)(Wsh + k * 68 + 4 * tn);
            float ss[4] = {s4.x, s4.y, s4.z, s4.w};
#pragma unroll
            for (int i = 0; i < 4; i++) {
                u64 si = pk(ss[i], ss[i]);
                pacc[i][0] = fma2(si, w2.x, pacc[i][0]);
                pacc[i][1] = fma2(si, w2.y, pacc[i][1]);
            }
        }
        float4 bv = *(const float4*)(ba1 + c * 64 + 4 * tn);
        float bb[4] = {bv.x, bv.y, bv.z, bv.w};
#pragma unroll
        for (int i = 0; i < 4; i++) {
            float p_[4];
            upk(pacc[i][0], p_[0], p_[1]);
            upk(pacc[i][1], p_[2], p_[3]);
#pragma unroll
            for (int jj = 0; jj < 4; jj++)
                Pt[(4 * tn + jj) * 36 + 4 * tb + i] = p_[jj] + bb[jj];
        }
    }

    // Main attention loop
    float m_run[4], l_run[4];
    u64 ctxa2[4][2] = {};
#pragma unroll
    for (int i = 0; i < 4; i++) { m_run[i] = -1e30f; l_run[i] = 0.f; }

    const float* npc = npT + (long)c * 64 * 1024;

    for (int nt = 0; nt < 1024; nt += 64) {
        __syncthreads();
#pragma unroll
        for (int r = 0; r < 8; r++) {
            int idx = tid + r * 128;
            int h = idx >> 4, q4 = idx & 15;
            *(float4*)(Qt + h * 68 + 4 * q4) = *(const float4*)(npc + (long)h * 1024 + nt + 4 * q4);
            *(float4*)(NE + h * 64 + 4 * q4) = *(const float4*)(ne + (long)(nt + h) * 64 + 4 * q4);
        }
        if (tid < 64) msk[tid] = mask[nt + tid];
        __syncthreads();

        u64 acc2[4][2] = {};
#pragma unroll 4
        for (int h = 0; h < 64; h++) {
            float4 p = *(const float4*)(Pt + h * 36 + 4 * tb);
            ulonglong2 q = *(const ulonglong2*)(Qt + h * 68 + 4 * tn);
            u64 w2 = ws2[h];
            float pp[4] = {p.x, p.y, p.z, p.w};
#pragma unroll
            for (int i = 0; i < 4; i++) {
                u64 pi2 = pk(pp[i], pp[i]);
                u64 t0 = add2(pi2, q.x);
                u64 t1 = add2(pi2, q.y);
                float a0, a1, b0f, b1f;
                upk(t0, a0, a1); upk(t1, b0f, b1f);
                a0 = fmaxf(a0, 0.f); a1 = fmaxf(a1, 0.f);
                b0f = fmaxf(b0f, 0.f); b1f = fmaxf(b1f, 0.f);
                acc2[i][0] = fma2(pk(a0, a1), w2, acc2[i][0]);
                acc2[i][1] = fma2(pk(b0f, b1f), w2, acc2[i][1]);
            }
        }
        __syncthreads();

        float* PB = Qt;
        float4 msk4 = *(const float4*)(msk + 4 * tn);
        float mk[4] = {msk4.x, msk4.y, msk4.z, msk4.w};
        float alpha[4];
#pragma unroll
        for (int i = 0; i < 4; i++) {
            float sc[4];
            upk(acc2[i][0], sc[0], sc[1]);
            upk(acc2[i][1], sc[2], sc[3]);
#pragma unroll
            for (int j = 0; j < 4; j++) sc[j] = (sc[j] + bias2) * mk[j];
            float mx = fmaxf(fmaxf(sc[0], sc[1]), fmaxf(sc[2], sc[3]));
#pragma unroll
            for (int o = 1; o < 16; o <<= 1) mx = fmaxf(mx, __shfl_xor_sync(0xffffffffu, mx, o));
            float mnew = fmaxf(m_run[i], mx);
            alpha[i] = __expf(m_run[i] - mnew);
            m_run[i] = mnew;
            float4 pv;
            pv.x = __expf(sc[0] - mnew);
            pv.y = __expf(sc[1] - mnew);
            pv.z = __expf(sc[2] - mnew);
            pv.w = __expf(sc[3] - mnew);
            *(float4*)(PB + (4 * tb + i) * 68 + 4 * tn) = pv;
            float s = pv.x + pv.y + pv.z + pv.w;
#pragma unroll
            for (int o = 1; o < 16; o <<= 1) s += __shfl_xor_sync(0xffffffffu, s, o);
            l_run[i] = l_run[i] * alpha[i] + s;
        }
        __syncthreads();

#pragma unroll
        for (int i = 0; i < 4; i++) {
            u64 al2 = pk(alpha[i], alpha[i]);
            ctxa2[i][0] = mul2(ctxa2[i][0], al2);
            ctxa2[i][1] = mul2(ctxa2[i][1], al2);
        }
        for (int n0 = 0; n0 < 64; n0 += 4) {
            float pbA[4][4];
#pragma unroll
            for (int i = 0; i < 4; i++) {
                float4 pv = *(const float4*)(PB + (4 * tb + i) * 68 + n0);
                pbA[i][0] = pv.x; pbA[i][1] = pv.y; pbA[i][2] = pv.z; pbA[i][3] = pv.w;
            }
#pragma unroll
            for (int k = 0; k < 4; k++) {
                ulonglong2 ne2 = *(const ulonglong2*)(NE + (n0 + k) * 64 + 4 * tn);
#pragma unroll
                for (int i = 0; i < 4; i++) {
                    u64 p2 = pk(pbA[i][k], pbA[i][k]);
                    ctxa2[i][0] = fma2(p2, ne2.x, ctxa2[i][0]);
                    ctxa2[i][1] = fma2(p2, ne2.y, ctxa2[i][1]);
                }
            }
        }
    }

    float* ctxc = ctx + ((long)c * 1024 + b0) * 64;
#pragma unroll
    for (int i = 0; i < 4; i++) {
        float inv = 1.f / l_run[i];
        float o_[4];
        upk(ctxa2[i][0], o_[0], o_[1]);
        upk(ctxa2[i][1], o_[2], o_[3]);
        *(float4*)(ctxc + (long)(4 * tb + i) * 64 + 4 * tn) =
            make_float4(o_[0] * inv, o_[1] * inv, o_[2] * inv, o_[3] * inv);
    }
}

// Fused gi-GEMM + gh-GEMM + GRU update.
__global__ void __launch_bounds__(256) gru_fused_kernel(
    const float* __restrict__ ctx, const float* __restrict__ s_in,
    const float* __restrict__ WihT, const float* __restrict__ WhhT,
    const float* __restrict__ bih, const float* __restrict__ bhh,
    float* __restrict__ s_out) {
    __shared__ float Ac[16 * 68];
    __shared__ float As_[16 * 68];
    __shared__ float Bi[16 * 192];
    __shared__ float Bh[16 * 192];
    const int c = blockIdx.y;
    const int r0 = blockIdx.x * 64;
    const float* ctxc = ctx + ((long)c * 1024 + r0) * 64;
    const float* sc_  = s_in + ((long)c * 1024 + r0) * 64;
    const float* wih = WihT + (long)c * 64 * 192;
    const float* whh = WhhT + (long)c * 64 * 192;
    const int tid = threadIdx.x, tb = tid >> 4, tn = tid & 15;

    u64 aI[4][3][2] = {};
    u64 aH[4][3][2] = {};

    for (int k0 = 0; k0 < 64; k0 += 16) {
        {
            int n = tid >> 2, kg = tid & 3;
            float4 av = *(const float4*)(ctxc + (long)n * 64 + k0 + 4 * kg);
            Ac[(4 * kg + 0) * 68 + n] = av.x;
            Ac[(4 * kg + 1) * 68 + n] = av.y;
            Ac[(4 * kg + 2) * 68 + n] = av.z;
            Ac[(4 * kg + 3) * 68 + n] = av.w;
            float4 sv = *(const float4*)(sc_ + (long)n * 64 + k0 + 4 * kg);
            As_[(4 * kg + 0) * 68 + n] = sv.x;
            As_[(4 * kg + 1) * 68 + n] = sv.y;
            As_[(4 * kg + 2) * 68 + n] = sv.z;
            As_[(4 * kg + 3) * 68 + n] = sv.w;
        }
#pragma unroll
        for (int r = 0; r < 3; r++) {
            int idx = tid + r * 256;
            int kk = idx / 48, c4 = idx % 48;
            *(float4*)(Bi + kk * 192 + 4 * c4) = *(const float4*)(wih + (long)(k0 + kk) * 192 + 4 * c4);
            *(float4*)(Bh + kk * 192 + 4 * c4) = *(const float4*)(whh + (long)(k0 + kk) * 192 + 4 * c4);
        }
        __syncthreads();
#pragma unroll 8
        for (int k = 0; k < 16; k++) {
            float4 a_c = *(const float4*)(Ac + k * 68 + 4 * tb);
            float4 a_s = *(const float4*)(As_ + k * 68 + 4 * tb);
            ulonglong2 bi0 = *(const ulonglong2*)(Bi + k * 192 + 4 * tn);
            ulonglong2 bi1 = *(const ulonglong2*)(Bi + k * 192 + 64 + 4 * tn);
            ulonglong2 bi2 = *(const ulonglong2*)(Bi + k * 192 + 128 + 4 * tn);
            ulonglong2 bh0 = *(const ulonglong2*)(Bh + k * 192 + 4 * tn);
            ulonglong2 bh1 = *(const ulonglong2*)(Bh + k * 192 + 64 + 4 * tn);
            ulonglong2 bh2 = *(const ulonglong2*)(Bh + k * 192 + 128 + 4 * tn);
            float ac[4] = {a_c.x, a_c.y, a_c.z, a_c.w};
            float as[4] = {a_s.x, a_s.y, a_s.z, a_s.w};
#pragma unroll
            for (int i = 0; i < 4; i++) {
                u64 aci = pk(ac[i], ac[i]);
                u64 asi = pk(as[i], as[i]);
                aI[i][0][0] = fma2(aci, bi0.x, aI[i][0][0]);
                aI[i][0][1] = fma2(aci, bi0.y, aI[i][0][1]);
                aI[i][1][0] = fma2(aci, bi1.x, aI[i][1][0]);
                aI[i][1][1] = fma2(aci, bi1.y, aI[i][1][1]);
                aI[i][2][0] = fma2(aci, bi2.x, aI[i][2][0]);
                aI[i][2][1] = fma2(aci, bi2.y, aI[i][2][1]);
                aH[i][0][0] = fma2(asi, bh0.x, aH[i][0][0]);
                aH[i][0][1] = fma2(asi, bh0.y, aH[i][0][1]);
                aH[i][1][0] = fma2(asi, bh1.x, aH[i][1][0]);
                aH[i][1][1] = fma2(asi, bh1.y, aH[i][1][1]);
                aH[i][2][0] = fma2(asi, bh2.x, aH[i][2][0]);
                aH[i][2][1] = fma2(asi, bh2.y, aH[i][2][1]);
            }
        }
        __syncthreads();
    }

    float4 bir4 = *(const float4*)(bih + (long)c * 192 + 4 * tn);
    float4 biz4 = *(const float4*)(bih + (long)c * 192 + 64 + 4 * tn);
    float4 bic4 = *(const float4*)(bih + (long)c * 192 + 128 + 4 * tn);
    float4 bhr4 = *(const float4*)(bhh + (long)c * 192 + 4 * tn);
    float4 bhz4 = *(const float4*)(bhh + (long)c * 192 + 64 + 4 * tn);
    float4 bhc4 = *(const float4*)(bhh + (long)c * 192 + 128 + 4 * tn);
    float bir[4] = {bir4.x, bir4.y, bir4.z, bir4.w};
    float biz[4] = {biz4.x, biz4.y, biz4.z, biz4.w};
    float bic[4] = {bic4.x, bic4.y, bic4.z, bic4.w};
    float bhr[4] = {bhr4.x, bhr4.y, bhr4.z, bhr4.w};
    float bhz[4] = {bhz4.x, bhz4.y, bhz4.z, bhz4.w};
    float bhc[4] = {bhc4.x, bhc4.y, bhc4.z, bhc4.w};

#pragma unroll
    for (int i = 0; i < 4; i++) {
        float ir[4], iz[4], ic[4], hr[4], hz[4], hc[4];
        upk(aI[i][0][0], ir[0], ir[1]); upk(aI[i][0][1], ir[2], ir[3]);
        upk(aI[i][1][0], iz[0], iz[1]); upk(aI[i][1][1], iz[2], iz[3]);
        upk(aI[i][2][0], ic[0], ic[1]); upk(aI[i][2][1], ic[2], ic[3]);
        upk(aH[i][0][0], hr[0], hr[1]); upk(aH[i][0][1], hr[2], hr[3]);
        upk(aH[i][1][0], hz[0], hz[1]); upk(aH[i][1][1], hz[2], hz[3]);
        upk(aH[i][2][0], hc[0], hc[1]); upk(aH[i][2][1], hc[2], hc[3]);
        float4 sold4 = *(const float4*)(sc_ + (long)(4 * tb + i) * 64 + 4 * tn);
        float sold[4] = {sold4.x, sold4.y, sold4.z, sold4.w};
        float o_[4];
#pragma unroll
        for (int jj = 0; jj < 4; jj++) {
            float rr = 1.f / (1.f + expf(-(ir[jj] + bir[jj] + hr[jj] + bhr[jj])));
            float zz = 1.f / (1.f + expf(-(iz[jj] + biz[jj] + hz[jj] + bhz[jj])));
            float cand = tanhf(ic[jj] + bic[jj] + rr * (hc[jj] + bhc[jj]));
            o_[jj] = (1.f - zz) * cand + zz * sold[jj];
        }
        *(float4*)(s_out + ((long)c * 1024 + r0 + 4 * tb + i) * 64 + 4 * tn) =
            make_float4(o_[0], o_[1], o_[2], o_[3]);
    }
}

__global__ void transpose_kernel(const float* __restrict__ s, float* __restrict__ out) {
    long idx = (long)blockIdx.x * blockDim.x + threadIdx.x;
    if (idx >= (long)CC * NN * HH) return;
    int c = (int)(idx >> 16), n = (int)((idx >> 6) & 1023), h = (int)(idx & 63);
    out[(long)n * (CC * HH) + c * HH + h] = s[idx];
}

__global__ void reduce_chains_kernel(const float* __restrict__ part, const float* __restrict__ bias,
                                     float* __restrict__ out) {
    int idx = blockIdx.x * blockDim.x + threadIdx.x;
    if (idx >= NN * HH) return;
    float s = bias[idx & 63];
#pragma unroll
    for (int c = 0; c < CC; c++) s += part[(long)c * NN * HH + idx];
    out[idx] = fmaxf(s, 0.f);
}

__global__ void attnpred_kernel(const float* __restrict__ final_, const float* __restrict__ stacked,
                                const float* __restrict__ Wp, const float* __restrict__ bp,
                                float* __restrict__ attn, float* __restrict__ pred) {
    int warp = threadIdx.x >> 5, lane = threadIdx.x & 31;
    int n = blockIdx.x * 4 + warp;
    if (n >= NN) return;
    const float* f = final_ + (long)n * 64;
    float f0 = f[lane], f1 = f[lane + 32];
    float lg[CC];
#pragma unroll
    for (int c = 0; c < CC; c++) {
        const float* st = stacked + (long)n * (CC * HH) + c * HH;
        float v = f0 * st[lane] + f1 * st[lane + 32];
#pragma unroll
        for (int o = 16; o; o >>= 1) v += __shfl_xor_sync(0xffffffffu, v, o);
        lg[c] = v;
    }
    float p = f0 * Wp[lane] + f1 * Wp[lane + 32];
#pragma unroll
    for (int o = 16; o; o >>= 1) p += __shfl_xor_sync(0xffffffffu, p, o);
    float mx = lg[0];
#pragma unroll
    for (int c = 1; c < CC; c++) mx = fmaxf(mx, lg[c]);
    float e[CC], s = 0.f;
#pragma unroll
    for (int c = 0; c < CC; c++) { e[c] = expf(lg[c] - mx); s += e[c]; }
    if (lane == 0) {
        float inv = 1.f / s;
#pragma unroll
        for (int c = 0; c < CC; c++) attn[(long)n * CC + c] = e[c] * inv;
        pred[n] = p + bp[0];
    }
}

extern "C" void kernel_launch(void* const* d_in, const int* in_sizes, int n_in,
                              void* d_out, int out_size) {
    const float* node_feats = (const float*)d_in[0];
    const int*   edges      = (const int*)d_in[1];
    const float* Wt1  = (const float*)d_in[2];
    const float* bt1  = (const float*)d_in[3];
    const float* Wt2  = (const float*)d_in[4];
    const float* bt2  = (const float*)d_in[5];
    const float* Wci  = (const float*)d_in[6];
    const float* bci  = (const float*)d_in[7];
    const float* Wa1  = (const float*)d_in[8];
    const float* ba1  = (const float*)d_in[9];
    const float* Wa2  = (const float*)d_in[10];
    const float* ba2  = (const float*)d_in[11];
    const float* Wih  = (const float*)d_in[12];
    const float* Whh  = (const float*)d_in[13];
    const float* bih  = (const float*)d_in[14];
    const float* bhh  = (const float*)d_in[15];
    const float* Wag1 = (const float*)d_in[16];
    const float* bag1 = (const float*)d_in[17];
    const float* Wag2 = (const float*)d_in[18];
    const float* bag2 = (const float*)d_in[19];
    const float* Wp   = (const float*)d_in[20];
    const float* bp   = (const float*)d_in[21];
    float* out = (float*)d_out;

    float* S = nullptr;
    cudaGetSymbolAddress((void**)&S, g_scratch);
    float* g_t1 = S + O_T1;     float* g_ne = S + O_NE;
    float* g_np = S + O_NP;     float* g_s = S + O_S;
    float* g_ctx = S + O_CTX;   float* g_WihT = S + O_WIHT;
    float* g_WhhT = S + O_WHHT; float* g_mask = S + O_MASK;
    float* g_npT = S + O_NPT;

    const long CH = (long)CC * NN * HH;
    int E = in_sizes[1] / 2;

    zero_kernel<<<4, 256>>>(g_mask, NN);
    scatter_mask_kernel<<<(E + 255) / 256, 256>>>(edges, E, g_mask);

    gemm_tiled<1><<<dim3(1, 16, 1), 256>>>(node_feats, 0, DD, Wt1, 0, HH, bt1, 0, g_t1, 0, HH, DD);
    gemm_tiled<1><<<dim3(1, 16, 1), 256>>>(g_t1, 0, HH, Wt2, 0, HH, bt2, 0, g_ne, 0, HH, HH);

    pack_kernel<<<256, 256>>>(Wih, Whh, g_WihT, g_WhhT);

    gemm_tiled<0><<<dim3(1, 16, CC), 256>>>(g_ne, 0, HH, Wci, 64, CC * HH, bci, 64,
                                            g_s, (long)NN * HH, HH, HH);
    gemm_tiled<0><<<dim3(1, 16, CC), 256>>>(g_ne, 0, HH, Wa1 + 64 * 64, 128 * 64, HH, nullptr, 0,
                                            g_np, (long)NN * HH, HH, HH);
    transpose_np_kernel<<<(int)(CH / 256), 256>>>(g_np, g_npT);

    int cur = 0;
    for (int step = 0; step < LL; step++) {
        float* s_in = g_s + (long)cur * CH;
        float* s_out = g_s + (long)(1 - cur) * CH;
        attn_step_kernel<<<dim3(32, CC), 128>>>(s_in, g_npT, g_ne, Wa1, ba1, Wa2, ba2,
                                                g_mask, g_ctx);
        gru_fused_kernel<<<dim3(16, CC), 256>>>(g_ctx, s_in, g_WihT, g_WhhT, bih, bhh, s_out);
        cur ^= 1;
    }
    float* s_fin = g_s + (long)cur * CH;

    transpose_kernel<<<(int)(CH / 256), 256>>>(s_fin, out + OUT_STACKED);

    gemm_tiled<0><<<dim3(1, 16, CC), 256>>>(s_fin, (long)NN * HH, HH,
                                            Wag1, 64 * 64, HH, nullptr, 0,
                                            g_ctx, (long)NN * HH, HH, HH);
    reduce_chains_kernel<<<NN * HH / 256, 256>>>(g_ctx, bag1, g_t1);

    gemm_tiled<0><<<dim3(1, 16, 1), 256>>>(g_t1, 0, HH, Wag2, 0, HH, bag2, 0,
                                           out + OUT_FINAL, 0, HH, HH);

    attnpred_kernel<<<NN / 4, 128>>>(out + OUT_FINAL, out + OUT_STACKED, Wp, bp,
                                     out + OUT_ATTN, out + OUT_PRED);
}